// round 16
// baseline (speedup 1.0000x reference)
#include <cuda_runtime.h>
#include <cuda_fp16.h>

// ---------------------------------------------------------------------------
// KNNGaussianBlur: out = GaussianBlur_sigma4_radius12(img[0]) with replicate
// padding. (/max ... *max cancels -> no reduction.)
//
// R16 = R15 (two-pass, fp16 row-pair-interleaved scratch, f32x2 both passes)
// + CROSS-KERNEL L2 REUSE (scratch = 100MB < 126MB L2):
//  * hblur runs in REVERSE launch order: its first reads are vblur's last
//    writes -> L2 hits instead of DRAM.
//  * hblur output stores __stcs (write-once) so 201MB of output doesn't
//    evict unread scratch; hblur scratch reads __ldcs (read-once).
//  * vblur input reads __ldcs (halo reuse is between concurrent neighbor
//    blocks only) so the 201MB input stream doesn't flush scratch from L2.
// ---------------------------------------------------------------------------

#define H_IMG 4096
#define W_IMG 4096
#define C_IMG 3
#define RADIUS 12

// 100.7 MB fp16 scratch, layout [C][H/2][W][2]: for row pair rp, position x:
// scratch[((c*2048+rp)*4096 + x)*2 + r] = vblur(row 2rp+r, x).
__device__ __half g_scratch[(size_t)C_IMG * H_IMG * W_IMG];

// 13 unique weights of the 25-tap Gaussian (sigma=4), normalized.
__device__ constexpr float KW[13] = {
    0.09990835f, 0.09683452f, 0.08816879f, 0.07541476f, 0.06059747f,
    0.04574137f, 0.03243549f, 0.02160670f, 0.01352113f, 0.00794866f,
    0.00438966f, 0.00227733f, 0.00110988f
};

__device__ __forceinline__ unsigned long long pack2(float lo, float hi) {
    unsigned long long r;
    asm("mov.b64 %0, {%1, %2};" : "=l"(r) : "f"(lo), "f"(hi));
    return r;
}
__device__ __forceinline__ void unpack2(unsigned long long v, float& lo, float& hi) {
    asm("mov.b64 {%0, %1}, %2;" : "=f"(lo), "=f"(hi) : "l"(v));
}
__device__ __forceinline__ void fma2(unsigned long long& acc,
                                     unsigned long long a, unsigned long long w) {
    asm("fma.rn.f32x2 %0, %1, %2, %0;" : "+l"(acc) : "l"(a), "l"(w));
}

// ------------------------------ Vertical pass ------------------------------
// Thread = one f4 column x 16 output rows (8 row pairs), streams 40 rows
// (row clamp = replicate pad). f32x2 accumulators. Input loads are
// streaming (__ldcs) so they don't evict scratch from L2; scratch stores
// use the default write-back policy (stay L2-resident for hblur).
constexpr int VROWS = 16;

__global__ __launch_bounds__(128)
void vblur_kernel(const float* __restrict__ in) {
    const int W4 = W_IMG / 4;                      // 1024
    int col4 = blockIdx.x * 128 + threadIdx.x;     // 0..1023
    int y0   = blockIdx.y * VROWS;
    int cch  = blockIdx.z;

    const float* incf = in + (size_t)cch * ((size_t)H_IMG * W_IMG);
    const ulonglong2* inc = (const ulonglong2*)incf;
    __half* outc = g_scratch + (size_t)cch * ((size_t)H_IMG * W_IMG);

    unsigned long long w2[13];
#pragma unroll
    for (int k = 0; k < 13; ++k) w2[k] = pack2(KW[k], KW[k]);

    unsigned long long aLo[VROWS], aHi[VROWS];
#pragma unroll
    for (int i = 0; i < VROWS; ++i) { aLo[i] = 0ull; aHi[i] = 0ull; }

#pragma unroll
    for (int rr = 0; rr < VROWS + 2 * RADIUS; ++rr) {
        int row = y0 - RADIUS + rr;
        row = row < 0 ? 0 : (row > H_IMG - 1 ? H_IMG - 1 : row);
        ulonglong2 v = __ldcs(&inc[(size_t)row * W4 + col4]);
#pragma unroll
        for (int i = 0; i < VROWS; ++i) {
            int d = rr - RADIUS - i;               // compile-time per (rr,i)
            if (d >= -RADIUS && d <= RADIUS) {
                unsigned long long w = w2[d < 0 ? -d : d];
                fma2(aLo[i], v.x, w);
                fma2(aHi[i], v.y, w);
            }
        }
    }

    // Interleaved store: pair i = rows (y0+2i, y0+2i+1). 8 halves per pair:
    // (r0.x, r1.x, r0.y, r1.y, r0.z, r1.z, r0.w, r1.w) = one uint4.
#pragma unroll
    for (int i = 0; i < VROWS / 2; ++i) {
        float a0x, a0y, a0z, a0w, a1x, a1y, a1z, a1w;
        unpack2(aLo[2 * i],     a0x, a0y); unpack2(aHi[2 * i],     a0z, a0w);
        unpack2(aLo[2 * i + 1], a1x, a1y); unpack2(aHi[2 * i + 1], a1z, a1w);
        __half2 p0 = __floats2half2_rn(a0x, a1x);
        __half2 p1 = __floats2half2_rn(a0y, a1y);
        __half2 p2 = __floats2half2_rn(a0z, a1z);
        __half2 p3 = __floats2half2_rn(a0w, a1w);
        uint4 pk = make_uint4(*(unsigned*)&p0, *(unsigned*)&p1,
                              *(unsigned*)&p2, *(unsigned*)&p3);
        size_t rp = (size_t)(y0 / 2 + i);
        *(uint4*)(outc + (rp * W_IMG + 4 * (size_t)col4) * 2) = pk;
    }
}

// ----------------------------- Horizontal pass -----------------------------
// Block = one row pair, REVERSE launch order (first blocks read vblur's
// most-recently-written scratch -> L2 hits). Thread owns 2 groups of 8 px x
// 2 rows; window = 8 contiguous LDG.128 (__ldcs, read-once). Output stores
// __stcs so they don't pollute L2. OOB uint4s broadcast the edge (r0,r1)
// pair (exact replicate padding).
__global__ __launch_bounds__(256)
void hblur_kernel(float* __restrict__ out) {
    int rp   = (H_IMG / 2 - 1) - blockIdx.x;       // reversed row pair
    int cch  = (C_IMG - 1) - blockIdx.y;           // reversed channel
    int w    = threadIdx.x >> 5;
    int lane = threadIdx.x & 31;

    const __half* inh = g_scratch
        + ((size_t)cch * (H_IMG / 2) + rp) * ((size_t)W_IMG * 2);
    const uint4* in4 = (const uint4*)inh;          // u covers x = 4u..4u+3

    unsigned long long w2[13];
#pragma unroll
    for (int k = 0; k < 13; ++k) w2[k] = pack2(KW[k], KW[k]);

#pragma unroll
    for (int g = 0; g < 2; ++g) {
        int b8   = 64 * w + 32 * g + lane;         // owned 8px slot 0..511
        int base = 8 * b8;                         // first output px

        unsigned long long acc[8];
#pragma unroll
        for (int p = 0; p < 8; ++p) acc[p] = 0ull;

#pragma unroll
        for (int j = 0; j < 8; ++j) {
            int u = 2 * b8 - 3 + j;                // x = 4u..4u+3
            uint4 q;
            if (u >= 0 && u < W_IMG / 4) {
                q = __ldcs(&in4[u]);
            } else {
                // whole uint4 OOB -> broadcast edge (r0,r1) pair
                unsigned pe = __ldg((const unsigned*)inh
                                    + (u < 0 ? 0 : W_IMG - 1));
                q = make_uint4(pe, pe, pe, pe);
            }
#pragma unroll
            for (int h = 0; h < 4; ++h) {
                unsigned uq = (h == 0) ? q.x : (h == 1) ? q.y
                            : (h == 2) ? q.z : q.w;
                float2 f = __half22float2(*(__half2*)&uq);  // (r0[x], r1[x])
                unsigned long long xv = pack2(f.x, f.y);
                int m = 4 * j + h;                 // x - (base-12), 0..31
#pragma unroll
                for (int p = 0; p < 8; ++p) {
                    int d = m - RADIUS - p;        // compile-time tap offset
                    if (d >= -RADIUS && d <= RADIUS)
                        fma2(acc[p], xv, w2[d < 0 ? -d : d]);
                }
            }
        }

        float lo[8], hi[8];
#pragma unroll
        for (int p = 0; p < 8; ++p) unpack2(acc[p], lo[p], hi[p]);

        float* o0 = out + ((size_t)cch * H_IMG + 2 * (size_t)rp) * W_IMG + base;
        float* o1 = o0 + W_IMG;
        __stcs((float4*)o0,       make_float4(lo[0], lo[1], lo[2], lo[3]));
        __stcs((float4*)(o0 + 4), make_float4(lo[4], lo[5], lo[6], lo[7]));
        __stcs((float4*)o1,       make_float4(hi[0], hi[1], hi[2], hi[3]));
        __stcs((float4*)(o1 + 4), make_float4(hi[4], hi[5], hi[6], hi[7]));
    }
}

// ------------------------------ entry point --------------------------------
extern "C" void kernel_launch(void* const* d_in, const int* in_sizes, int n_in,
                              void* d_out, int out_size) {
    const float* img = (const float*)d_in[0];      // [1,3,4096,4096] fp32
    float* out = (float*)d_out;                    // [3,4096,4096] fp32

    dim3 vgrid(W_IMG / 4 / 128, H_IMG / VROWS, C_IMG);   // (8, 256, 3)
    vblur_kernel<<<vgrid, 128>>>(img);

    dim3 hgrid(H_IMG / 2, C_IMG);                        // (2048, 3)
    hblur_kernel<<<hgrid, 256>>>(out);
}

// round 17
// speedup vs baseline: 1.2774x; 1.2774x over previous
#include <cuda_runtime.h>
#include <cuda_fp16.h>

// ---------------------------------------------------------------------------
// KNNGaussianBlur: out = GaussianBlur_sigma4_radius12(img[0]) with replicate
// padding. (/max ... *max cancels -> no reduction.)
//
// R17 = R15 (best: two-pass, fp16 row-pair-interleaved scratch, f32x2 both
// passes, 110.6us) with R16's cache hints REVERTED (ldcs on vblur input
// destroyed the vertical-halo L2 reuse: vblur 54->85us) and ONE change:
// hblur SOFTWARE-PIPELINES its two 8px groups -- all 16 window loads issue
// before any compute, so group B's DRAM latency hides under group A's FMAs.
// ---------------------------------------------------------------------------

#define H_IMG 4096
#define W_IMG 4096
#define C_IMG 3
#define RADIUS 12

// 100.7 MB fp16 scratch, layout [C][H/2][W][2]: for row pair rp, position x:
// scratch[((c*2048+rp)*4096 + x)*2 + r] = vblur(row 2rp+r, x).
__device__ __half g_scratch[(size_t)C_IMG * H_IMG * W_IMG];

// 13 unique weights of the 25-tap Gaussian (sigma=4), normalized.
__device__ constexpr float KW[13] = {
    0.09990835f, 0.09683452f, 0.08816879f, 0.07541476f, 0.06059747f,
    0.04574137f, 0.03243549f, 0.02160670f, 0.01352113f, 0.00794866f,
    0.00438966f, 0.00227733f, 0.00110988f
};

__device__ __forceinline__ unsigned long long pack2(float lo, float hi) {
    unsigned long long r;
    asm("mov.b64 %0, {%1, %2};" : "=l"(r) : "f"(lo), "f"(hi));
    return r;
}
__device__ __forceinline__ void unpack2(unsigned long long v, float& lo, float& hi) {
    asm("mov.b64 {%0, %1}, %2;" : "=f"(lo), "=f"(hi) : "l"(v));
}
__device__ __forceinline__ void fma2(unsigned long long& acc,
                                     unsigned long long a, unsigned long long w) {
    asm("fma.rn.f32x2 %0, %1, %2, %0;" : "+l"(acc) : "l"(a), "l"(w));
}

// ------------------------------ Vertical pass ------------------------------
// R15's exact kernel: thread = one f4 column x 16 output rows (8 row pairs),
// streams 40 rows (row clamp = replicate pad), f32x2 accumulators, default
// cache policy everywhere (halo re-reads between neighbor blocks hit L2).
constexpr int VROWS = 16;

__global__ __launch_bounds__(128)
void vblur_kernel(const float* __restrict__ in) {
    const int W4 = W_IMG / 4;                      // 1024
    int col4 = blockIdx.x * 128 + threadIdx.x;     // 0..1023
    int y0   = blockIdx.y * VROWS;
    int cch  = blockIdx.z;

    const float* incf = in + (size_t)cch * ((size_t)H_IMG * W_IMG);
    const ulonglong2* inc = (const ulonglong2*)incf;
    __half* outc = g_scratch + (size_t)cch * ((size_t)H_IMG * W_IMG);

    unsigned long long w2[13];
#pragma unroll
    for (int k = 0; k < 13; ++k) w2[k] = pack2(KW[k], KW[k]);

    unsigned long long aLo[VROWS], aHi[VROWS];
#pragma unroll
    for (int i = 0; i < VROWS; ++i) { aLo[i] = 0ull; aHi[i] = 0ull; }

#pragma unroll
    for (int rr = 0; rr < VROWS + 2 * RADIUS; ++rr) {
        int row = y0 - RADIUS + rr;
        row = row < 0 ? 0 : (row > H_IMG - 1 ? H_IMG - 1 : row);
        ulonglong2 v = __ldg(&inc[(size_t)row * W4 + col4]);
#pragma unroll
        for (int i = 0; i < VROWS; ++i) {
            int d = rr - RADIUS - i;               // compile-time per (rr,i)
            if (d >= -RADIUS && d <= RADIUS) {
                unsigned long long w = w2[d < 0 ? -d : d];
                fma2(aLo[i], v.x, w);
                fma2(aHi[i], v.y, w);
            }
        }
    }

    // Interleaved store: pair i = rows (y0+2i, y0+2i+1). 8 halves per pair:
    // (r0.x, r1.x, r0.y, r1.y, r0.z, r1.z, r0.w, r1.w) = one uint4.
#pragma unroll
    for (int i = 0; i < VROWS / 2; ++i) {
        float a0x, a0y, a0z, a0w, a1x, a1y, a1z, a1w;
        unpack2(aLo[2 * i],     a0x, a0y); unpack2(aHi[2 * i],     a0z, a0w);
        unpack2(aLo[2 * i + 1], a1x, a1y); unpack2(aHi[2 * i + 1], a1z, a1w);
        __half2 p0 = __floats2half2_rn(a0x, a1x);
        __half2 p1 = __floats2half2_rn(a0y, a1y);
        __half2 p2 = __floats2half2_rn(a0z, a1z);
        __half2 p3 = __floats2half2_rn(a0w, a1w);
        uint4 pk = make_uint4(*(unsigned*)&p0, *(unsigned*)&p1,
                              *(unsigned*)&p2, *(unsigned*)&p3);
        size_t rp = (size_t)(y0 / 2 + i);
        *(uint4*)(outc + (rp * W_IMG + 4 * (size_t)col4) * 2) = pk;
    }
}

// ----------------------------- Horizontal pass -----------------------------
// Block = one row pair; thread owns TWO 8px-x-2row groups. NEW: both groups'
// windows (8 LDG.128 each) are loaded BEFORE any compute -> group B's load
// latency hides under group A's 200 fma2. Every loaded half2 converts
// straight into the (row0,row1) f32x2 operand. OOB uint4s broadcast the
// edge (r0,r1) pair (exact replicate padding).
__device__ __forceinline__ void h_load_window(const uint4* in4,
                                              const __half* inh,
                                              int b8, uint4* q) {
#pragma unroll
    for (int j = 0; j < 8; ++j) {
        int u = 2 * b8 - 3 + j;                    // covers x = 4u..4u+3
        if (u >= 0 && u < W_IMG / 4) {
            q[j] = __ldg(&in4[u]);
        } else {
            unsigned pe = __ldg((const unsigned*)inh
                                + (u < 0 ? 0 : W_IMG - 1));
            q[j] = make_uint4(pe, pe, pe, pe);
        }
    }
}

__device__ __forceinline__ void h_compute_store(const uint4* q,
                                                const unsigned long long* w2,
                                                float* o0, float* o1) {
    unsigned long long acc[8];
#pragma unroll
    for (int p = 0; p < 8; ++p) acc[p] = 0ull;

#pragma unroll
    for (int j = 0; j < 8; ++j) {
#pragma unroll
        for (int h = 0; h < 4; ++h) {
            unsigned uq = (h == 0) ? q[j].x : (h == 1) ? q[j].y
                        : (h == 2) ? q[j].z : q[j].w;
            float2 f = __half22float2(*(__half2*)&uq);   // (r0[x], r1[x])
            unsigned long long xv = pack2(f.x, f.y);
            int m = 4 * j + h;                     // x - (base-12), 0..31
#pragma unroll
            for (int p = 0; p < 8; ++p) {
                int d = m - RADIUS - p;            // compile-time tap offset
                if (d >= -RADIUS && d <= RADIUS)
                    fma2(acc[p], xv, w2[d < 0 ? -d : d]);
            }
        }
    }

    float lo[8], hi[8];
#pragma unroll
    for (int p = 0; p < 8; ++p) unpack2(acc[p], lo[p], hi[p]);
    *(float4*)o0       = make_float4(lo[0], lo[1], lo[2], lo[3]);
    *(float4*)(o0 + 4) = make_float4(lo[4], lo[5], lo[6], lo[7]);
    *(float4*)o1       = make_float4(hi[0], hi[1], hi[2], hi[3]);
    *(float4*)(o1 + 4) = make_float4(hi[4], hi[5], hi[6], hi[7]);
}

__global__ __launch_bounds__(256)
void hblur_kernel(float* __restrict__ out) {
    int rp   = blockIdx.x;                         // row pair 0..2047
    int cch  = blockIdx.y;
    int w    = threadIdx.x >> 5;
    int lane = threadIdx.x & 31;

    const __half* inh = g_scratch
        + ((size_t)cch * (H_IMG / 2) + rp) * ((size_t)W_IMG * 2);
    const uint4* in4 = (const uint4*)inh;

    unsigned long long w2[13];
#pragma unroll
    for (int k = 0; k < 13; ++k) w2[k] = pack2(KW[k], KW[k]);

    int b8a = 64 * w + lane;                       // group A slot
    int b8b = b8a + 32;                            // group B slot

    // Software pipeline: all 16 loads in flight before any FMA.
    uint4 qa[8], qb[8];
    h_load_window(in4, inh, b8a, qa);
    h_load_window(in4, inh, b8b, qb);

    size_t obase = ((size_t)cch * H_IMG + 2 * (size_t)rp) * W_IMG;
    float* oa0 = out + obase + 8 * b8a;
    float* ob0 = out + obase + 8 * b8b;

    h_compute_store(qa, w2, oa0, oa0 + W_IMG);
    h_compute_store(qb, w2, ob0, ob0 + W_IMG);
}

// ------------------------------ entry point --------------------------------
extern "C" void kernel_launch(void* const* d_in, const int* in_sizes, int n_in,
                              void* d_out, int out_size) {
    const float* img = (const float*)d_in[0];      // [1,3,4096,4096] fp32
    float* out = (float*)d_out;                    // [3,4096,4096] fp32

    dim3 vgrid(W_IMG / 4 / 128, H_IMG / VROWS, C_IMG);   // (8, 256, 3)
    vblur_kernel<<<vgrid, 128>>>(img);

    dim3 hgrid(H_IMG / 2, C_IMG);                        // (2048, 3)
    hblur_kernel<<<hgrid, 256>>>(out);
}